// round 16
// baseline (speedup 1.0000x reference)
#include <cuda_runtime.h>
#include <cuda_fp16.h>
#include <cstdint>
#include <cstddef>

// ============================================================================
// StackedLoRALinear on GB300 — family-target build (no tcgen05).
// R5 tf32 2554us -> R7 fp16 mma 1719us -> R8 ldmatrix+2CTA/SM 1425us
// -> R9 LoRA folded into W' (single K=3072 GEMM) 1303us. R12 (4-warp CTAs)
// regressed; R14 streaming stores neutral.
// R15: attack CTA quantization: 3072 tiles / 296 slots = 10.38 -> 6% tail.
//   BM=64 tiles (6144 CTAs), 2-stage pipe (55.3KB smem) -> 3 CTAs/SM,
//   6 warps/SMSP, tail shrinks to 1.2%. Warp tile 32x32, acc=32 regs.
// ============================================================================

#define DEV __device__ __forceinline__

static constexpr int D_DIM  = 3072;
static constexpr int M_ROWS = 16384;     // 4 * 4096
static constexpr int R_DIM  = 128;       // depth * rank

static constexpr int BM = 64, BN = 128, BK = 64;
static constexpr int NTHREADS = 256;                // 8 warps, 2(M) x 4(N)
static constexpr int STAGES = 2;
static constexpr int SROWH  = 72;                   // smem halves/row: 64 + 8 pad
static constexpr int ROW_B  = SROWH * 2;            // 144 B (conflict-free)
static constexpr int PLANE_A = BM * ROW_B;          // 9216 B
static constexpr int PLANE_B = BN * ROW_B;          // 18432 B
static constexpr int STAGE_B = PLANE_A + PLANE_B;   // 27648 B
static constexpr int SMEM_B  = STAGES * STAGE_B;    // 55296 B -> 3 CTAs/SM

// ---------------- scratch (static device globals; no allocation) ------------
__device__ __align__(16) __half g_xh [(size_t)M_ROWS * D_DIM];  // 100.7 MB
__device__ __align__(16) __half g_Wph[(size_t)D_DIM * D_DIM];   // 18.9 MB (W')
__device__ __align__(16) __half g_AfT[(size_t)D_DIM * R_DIM];   // 0.75 MB A^T
__device__ __align__(16) __half g_Bph[(size_t)D_DIM * R_DIM];   // 0.75 MB

// ---------------- helpers ----------------------------------------------------
DEV uint32_t smem_u32(const void* p) {
    uint32_t a;
    asm("{ .reg .u64 t; cvta.to.shared.u64 t, %1; cvt.u32.u64 %0, t; }"
        : "=r"(a) : "l"(p));
    return a;
}

DEV void cp16(uint32_t s, const void* g) {
    asm volatile("cp.async.cg.shared.global [%0], [%1], 16;\n" :: "r"(s), "l"(g));
}

DEV void ldsm4(uint32_t& r0, uint32_t& r1, uint32_t& r2, uint32_t& r3,
               uint32_t addr) {
    asm volatile("ldmatrix.sync.aligned.m8n8.x4.shared.b16 {%0,%1,%2,%3}, [%4];"
                 : "=r"(r0), "=r"(r1), "=r"(r2), "=r"(r3) : "r"(addr));
}

DEV void mma16816(float c[4],
                  uint32_t a0, uint32_t a1, uint32_t a2, uint32_t a3,
                  uint32_t b0, uint32_t b1) {
    asm volatile(
        "mma.sync.aligned.m16n8k16.row.col.f32.f16.f16.f32 "
        "{%0,%1,%2,%3},{%4,%5,%6,%7},{%8,%9},{%0,%1,%2,%3};"
        : "+f"(c[0]), "+f"(c[1]), "+f"(c[2]), "+f"(c[3])
        : "r"(a0), "r"(a1), "r"(a2), "r"(a3), "r"(b0), "r"(b1));
}

DEV void stcs2(float* p, float vx, float vy) {
    asm volatile("st.global.cs.v2.f32 [%0], {%1,%2};"
                 :: "l"(p), "f"(vx), "f"(vy) : "memory");
}

// ---------------- prep: x -> fp16; pack A^T and Bp as fp16 ------------------
__global__ void prep_kernel(const float* __restrict__ x,
                            const float* __restrict__ lA,
                            const float* __restrict__ lB) {
    const size_t stride = (size_t)gridDim.x * blockDim.x;
    const size_t g0 = (size_t)blockIdx.x * blockDim.x + threadIdx.x;
    for (size_t i = g0; i < (size_t)M_ROWS * D_DIM / 4; i += stride) {
        float4 v = reinterpret_cast<const float4*>(x)[i];
        __half2 h0 = __floats2half2_rn(v.x, v.y);
        __half2 h1 = __floats2half2_rn(v.z, v.w);
        reinterpret_cast<uint2*>(g_xh)[i] =
            make_uint2(*(uint32_t*)&h0, *(uint32_t*)&h1);
    }
    for (size_t idx = g0; idx < (size_t)D_DIM * R_DIM; idx += stride) {
        int j = (int)(idx / D_DIM), i = (int)(idx % D_DIM);
        g_AfT[(size_t)i * R_DIM + j] = __float2half_rn(lA[idx]);
    }
    for (size_t idx = g0; idx < (size_t)D_DIM * R_DIM; idx += stride) {
        int n = (int)(idx >> 7), j = (int)(idx & 127);
        int d = j >> 5, r = j & 31;
        g_Bph[idx] = __float2half_rn(lB[(size_t)(d * D_DIM + n) * 32 + r]);
    }
}

// ---------------- fp16 GEMM, fp32 accum --------------------------------------
// C[m][n] = bias[n] + Madd[m][n] + sum_K A1[m,k]*B1[n,k]
// CTA 64x128, 8 warps (2M x 4N), warp tile 32x32, BK=64, 2-stage cp.async,
// ldmatrix fragment loads, 3 CTAs/SM (6 warps/SMSP).
template<bool OUTH, bool ADDM>
__global__ void __launch_bounds__(NTHREADS, 3)
gemm_f16(const __half* __restrict__ A1, int lda,
         const __half* __restrict__ B1, int ldb, int K,
         const float* __restrict__ bias, const float* __restrict__ Madd,
         void* __restrict__ Cout, int ldc)
{
    extern __shared__ __align__(16) char smem[];
    const uint32_t sbase = smem_u32(smem);
    const int tid  = threadIdx.x;
    const int wid  = tid >> 5, lane = tid & 31;
    const int g    = lane >> 2, t = lane & 3;
    const int wm   = (wid & 1) * 32, wn = (wid >> 1) * 32;
    const int mBase = blockIdx.y * BM, nBase = blockIdx.x * BN;
    const int NT = K / BK;
    // loader: A 2 chunks/thread, B 4 chunks/thread (16B chunks)
    const int arow = tid >> 2, ac = (tid & 3) * 2;
    const int brow = tid >> 1, bc = (tid & 1) * 4;

    // ldmatrix per-lane base offsets (halves)
    const uint32_t aRow = (uint32_t)(lane & 15);
    const uint32_t aKof = (uint32_t)((lane >> 4) << 3);
    const uint32_t bRow = (uint32_t)(((lane >> 4) << 3) + (lane & 7));
    const uint32_t bKof = (uint32_t)(((lane >> 3) & 1) << 3);

    float acc[2][4][4];
    #pragma unroll
    for (int mi = 0; mi < 2; ++mi)
        #pragma unroll
        for (int ni = 0; ni < 4; ++ni)
            #pragma unroll
            for (int c = 0; c < 4; ++c) acc[mi][ni][c] = 0.f;

    auto load_tile = [&](int kt) {
        if (kt < NT) {
            const int kOff = kt * BK;
            const uint32_t st = sbase + (uint32_t)((kt & 1) * STAGE_B);
            const __half* ga = A1 + (size_t)(mBase + arow) * lda + kOff + ac * 8;
            #pragma unroll
            for (int c = 0; c < 2; ++c)
                cp16(st + (uint32_t)(arow * ROW_B + (ac + c) * 16), ga + c * 8);
            const __half* gb = B1 + (size_t)(nBase + brow) * ldb + kOff + bc * 8;
            #pragma unroll
            for (int c = 0; c < 4; ++c)
                cp16(st + (uint32_t)(PLANE_A + brow * ROW_B + (bc + c) * 16),
                     gb + c * 8);
        }
        asm volatile("cp.async.commit_group;\n" ::: "memory");
    };

    load_tile(0);

    for (int kt = 0; kt < NT; ++kt) {
        __syncthreads();              // readers of slot (kt+1)&1 (iter kt-1) done
        load_tile(kt + 1);
        asm volatile("cp.async.wait_group 1;\n" ::: "memory");  // tile kt ready
        __syncthreads();

        const uint32_t stA = sbase + (uint32_t)((kt & 1) * STAGE_B);
        const uint32_t stB = stA + (uint32_t)PLANE_A;

        #pragma unroll
        for (int k16 = 0; k16 < BK; k16 += 16) {
            uint32_t a[2][4], b[4][2];
            #pragma unroll
            for (int mi = 0; mi < 2; ++mi) {
                const uint32_t addr = stA +
                    ((uint32_t)(wm + mi * 16) + aRow) * ROW_B +
                    ((uint32_t)k16 + aKof) * 2;
                ldsm4(a[mi][0], a[mi][1], a[mi][2], a[mi][3], addr);
            }
            #pragma unroll
            for (int np = 0; np < 2; ++np) {           // n-pair: ni = 2np, 2np+1
                const uint32_t addr = stB +
                    ((uint32_t)(wn + np * 16) + bRow) * ROW_B +
                    ((uint32_t)k16 + bKof) * 2;
                ldsm4(b[2 * np][0], b[2 * np][1],
                      b[2 * np + 1][0], b[2 * np + 1][1], addr);
            }
            #pragma unroll
            for (int mi = 0; mi < 2; ++mi)
                #pragma unroll
                for (int ni = 0; ni < 4; ++ni)
                    mma16816(acc[mi][ni],
                             a[mi][0], a[mi][1], a[mi][2], a[mi][3],
                             b[ni][0], b[ni][1]);
        }
    }

    // -------- epilogue -------------------------------------------------------
    #pragma unroll
    for (int mi = 0; mi < 2; ++mi) {
        const int m0 = mBase + wm + mi * 16 + g;
        #pragma unroll
        for (int ni = 0; ni < 4; ++ni) {
            const int n0 = nBase + wn + ni * 8 + 2 * t;
            float v0x = acc[mi][ni][0], v0y = acc[mi][ni][1];
            float v1x = acc[mi][ni][2], v1y = acc[mi][ni][3];
            if (bias) {
                const float2 bv = *reinterpret_cast<const float2*>(bias + n0);
                v0x += bv.x; v0y += bv.y; v1x += bv.x; v1y += bv.y;
            }
            if (ADDM) {
                const float2 w0 =
                    *reinterpret_cast<const float2*>(Madd + (size_t)m0 * ldc + n0);
                const float2 w1 =
                    *reinterpret_cast<const float2*>(Madd + (size_t)(m0 + 8) * ldc + n0);
                v0x += w0.x; v0y += w0.y; v1x += w1.x; v1y += w1.y;
            }
            if (OUTH) {
                __half* C = (__half*)Cout;
                *reinterpret_cast<__half2*>(C + (size_t)m0 * ldc + n0) =
                    __floats2half2_rn(v0x, v0y);
                *reinterpret_cast<__half2*>(C + (size_t)(m0 + 8) * ldc + n0) =
                    __floats2half2_rn(v1x, v1y);
            } else {
                float* C = (float*)Cout;
                stcs2(C + (size_t)m0 * ldc + n0,       v0x, v0y);
                stcs2(C + (size_t)(m0 + 8) * ldc + n0, v1x, v1y);
            }
        }
    }
}

// ---------------- launch -----------------------------------------------------
extern "C" void kernel_launch(void* const* d_in, const int* in_sizes, int n_in,
                              void* d_out, int out_size) {
    const float* x  = (const float*)d_in[0];   // [4,4096,3072]
    const float* W  = (const float*)d_in[1];   // [3072,3072]
    const float* b  = (const float*)d_in[2];   // [3072]
    const float* lA = (const float*)d_in[3];   // [4,32,3072]
    const float* lB = (const float*)d_in[4];   // [4,3072,32]
    float* out = (float*)d_out;                // [4,4096,3072]

    void *xh, *Wph, *AfT, *Bph;
    cudaGetSymbolAddress(&xh,  g_xh);
    cudaGetSymbolAddress(&Wph, g_Wph);
    cudaGetSymbolAddress(&AfT, g_AfT);
    cudaGetSymbolAddress(&Bph, g_Bph);

    cudaFuncSetAttribute((const void*)gemm_f16<false, false>,
                         cudaFuncAttributeMaxDynamicSharedMemorySize, SMEM_B);
    cudaFuncSetAttribute((const void*)gemm_f16<true, true>,
                         cudaFuncAttributeMaxDynamicSharedMemorySize, SMEM_B);

    // 1) fp16 conversions + packs (x, A^T, Bp); W stays fp32 for the fold
    prep_kernel<<<4096, 256>>>(x, lA, lB);

    // 2) W' = W + Bp @ Aflat   (M=3072, N=3072, K=128) -> fp16 W'
    gemm_f16<true, true><<<dim3(D_DIM / BN, D_DIM / BM), NTHREADS, SMEM_B>>>(
        (const __half*)Bph, R_DIM, (const __half*)AfT, R_DIM, R_DIM,
        nullptr, W, Wph, D_DIM);

    // 3) out = x @ W'^T + b   (M=16384, N=3072, K=3072)
    gemm_f16<false, false><<<dim3(D_DIM / BN, M_ROWS / BM), NTHREADS, SMEM_B>>>(
        (const __half*)xh, D_DIM, (const __half*)Wph, D_DIM, D_DIM,
        b, nullptr, out, D_DIM);
}

// round 17
// speedup vs baseline: 1.1798x; 1.1798x over previous
#include <cuda_runtime.h>
#include <cuda_fp16.h>
#include <cstdint>
#include <cstddef>

// ============================================================================
// StackedLoRALinear on GB300 — family-target build (no tcgen05).
// Path: R5 tf32 2554 -> R7 fp16 mma 1719 -> R8 ldmatrix+2CTA 1425
// -> R9 LoRA folded into W' (one K=3072 GEMM) 1303.
// R12 (4-warp CTAs) +17%; R15 (BM=64/2-stage/3CTA) +14% — both reverted.
// R16: keep the proven R9 shape (8 warps, 3 stages, 2 CTAs/SM) and fix ONLY
// the wave-tail: BN 128->96 => 4096 tiles / 296 slots: tail +6.0% -> +1.2%.
// Warp tile 64x24 (4 m-tiles x 3 n-tiles), acc 48 regs (more headroom).
// ============================================================================

#define DEV __device__ __forceinline__

static constexpr int D_DIM  = 3072;
static constexpr int M_ROWS = 16384;     // 4 * 4096
static constexpr int R_DIM  = 128;       // depth * rank

static constexpr int BM = 128, BN = 96, BK = 64;
static constexpr int NTHREADS = 256;                // 8 warps, 2(M) x 4(N)
static constexpr int STAGES = 3;
static constexpr int SROWH  = 72;                   // smem halves/row: 64 + 8 pad
static constexpr int ROW_B  = SROWH * 2;            // 144 B (conflict-free)
static constexpr int PLANE_A = BM * ROW_B;          // 18432 B
static constexpr int PLANE_B = BN * ROW_B;          // 13824 B
static constexpr int STAGE_B = PLANE_A + PLANE_B;   // 32256 B
static constexpr int SMEM_B  = STAGES * STAGE_B;    // 96768 B -> 2 CTAs/SM

// ---------------- scratch (static device globals; no allocation) ------------
__device__ __align__(16) __half g_xh [(size_t)M_ROWS * D_DIM];  // 100.7 MB
__device__ __align__(16) __half g_Wph[(size_t)D_DIM * D_DIM];   // 18.9 MB (W')
__device__ __align__(16) __half g_AfT[(size_t)D_DIM * R_DIM];   // 0.75 MB A^T
__device__ __align__(16) __half g_Bph[(size_t)D_DIM * R_DIM];   // 0.75 MB

// ---------------- helpers ----------------------------------------------------
DEV uint32_t smem_u32(const void* p) {
    uint32_t a;
    asm("{ .reg .u64 t; cvta.to.shared.u64 t, %1; cvt.u32.u64 %0, t; }"
        : "=r"(a) : "l"(p));
    return a;
}

DEV void cp16(uint32_t s, const void* g) {
    asm volatile("cp.async.cg.shared.global [%0], [%1], 16;\n" :: "r"(s), "l"(g));
}

DEV void ldsm4(uint32_t& r0, uint32_t& r1, uint32_t& r2, uint32_t& r3,
               uint32_t addr) {
    asm volatile("ldmatrix.sync.aligned.m8n8.x4.shared.b16 {%0,%1,%2,%3}, [%4];"
                 : "=r"(r0), "=r"(r1), "=r"(r2), "=r"(r3) : "r"(addr));
}

DEV void ldsm2(uint32_t& r0, uint32_t& r1, uint32_t addr) {
    asm volatile("ldmatrix.sync.aligned.m8n8.x2.shared.b16 {%0,%1}, [%2];"
                 : "=r"(r0), "=r"(r1) : "r"(addr));
}

DEV void mma16816(float c[4],
                  uint32_t a0, uint32_t a1, uint32_t a2, uint32_t a3,
                  uint32_t b0, uint32_t b1) {
    asm volatile(
        "mma.sync.aligned.m16n8k16.row.col.f32.f16.f16.f32 "
        "{%0,%1,%2,%3},{%4,%5,%6,%7},{%8,%9},{%0,%1,%2,%3};"
        : "+f"(c[0]), "+f"(c[1]), "+f"(c[2]), "+f"(c[3])
        : "r"(a0), "r"(a1), "r"(a2), "r"(a3), "r"(b0), "r"(b1));
}

DEV void stcs2(float* p, float vx, float vy) {
    asm volatile("st.global.cs.v2.f32 [%0], {%1,%2};"
                 :: "l"(p), "f"(vx), "f"(vy) : "memory");
}

// ---------------- prep: x -> fp16; pack A^T and Bp as fp16 ------------------
__global__ void prep_kernel(const float* __restrict__ x,
                            const float* __restrict__ lA,
                            const float* __restrict__ lB) {
    const size_t stride = (size_t)gridDim.x * blockDim.x;
    const size_t g0 = (size_t)blockIdx.x * blockDim.x + threadIdx.x;
    for (size_t i = g0; i < (size_t)M_ROWS * D_DIM / 4; i += stride) {
        float4 v = reinterpret_cast<const float4*>(x)[i];
        __half2 h0 = __floats2half2_rn(v.x, v.y);
        __half2 h1 = __floats2half2_rn(v.z, v.w);
        reinterpret_cast<uint2*>(g_xh)[i] =
            make_uint2(*(uint32_t*)&h0, *(uint32_t*)&h1);
    }
    for (size_t idx = g0; idx < (size_t)D_DIM * R_DIM; idx += stride) {
        int j = (int)(idx / D_DIM), i = (int)(idx % D_DIM);
        g_AfT[(size_t)i * R_DIM + j] = __float2half_rn(lA[idx]);
    }
    for (size_t idx = g0; idx < (size_t)D_DIM * R_DIM; idx += stride) {
        int n = (int)(idx >> 7), j = (int)(idx & 127);
        int d = j >> 5, r = j & 31;
        g_Bph[idx] = __float2half_rn(lB[(size_t)(d * D_DIM + n) * 32 + r]);
    }
}

// ---------------- fp16 GEMM, fp32 accum --------------------------------------
// C[m][n] = bias[n] + Madd[m][n] + sum_K A1[m,k]*B1[n,k]
// CTA 128x96, 8 warps (2M x 4N), warp tile 64x24, BK=64, 3-stage cp.async,
// ldmatrix fragment loads, 2 CTAs/SM (4 warps/SMSP).
template<bool OUTH, bool ADDM>
__global__ void __launch_bounds__(NTHREADS, 2)
gemm_f16(const __half* __restrict__ A1, int lda,
         const __half* __restrict__ B1, int ldb, int K,
         const float* __restrict__ bias, const float* __restrict__ Madd,
         void* __restrict__ Cout, int ldc)
{
    extern __shared__ __align__(16) char smem[];
    const uint32_t sbase = smem_u32(smem);
    const int tid  = threadIdx.x;
    const int wid  = tid >> 5, lane = tid & 31;
    const int g    = lane >> 2, t = lane & 3;
    const int wm   = (wid & 1) * 64, wn = (wid >> 1) * 24;
    const int mBase = blockIdx.y * BM, nBase = blockIdx.x * BN;
    const int NT = K / BK;

    // loaders (16B chunks, 8 per 128B row): A 1024 chunks, B 768 chunks
    const int arow = tid >> 1, acol = (tid & 1) * 4;   // 4 chunks/thread
    // B: 3 chunks/thread, chunk id = tid + i*256

    // ldmatrix per-lane base offsets (halves)
    const uint32_t aRow = (uint32_t)(lane & 15);
    const uint32_t aKof = (uint32_t)((lane >> 4) << 3);
    const uint32_t bRow = (uint32_t)(((lane >> 4) << 3) + (lane & 7));
    const uint32_t bKof = (uint32_t)(((lane >> 3) & 1) << 3);
    const uint32_t b2Row = (uint32_t)(lane & 7);              // x2 variant
    const uint32_t b2Kof = (uint32_t)(((lane >> 3) & 1) << 3);

    float acc[4][3][4];
    #pragma unroll
    for (int mi = 0; mi < 4; ++mi)
        #pragma unroll
        for (int ni = 0; ni < 3; ++ni)
            #pragma unroll
            for (int c = 0; c < 4; ++c) acc[mi][ni][c] = 0.f;

    auto load_tile = [&](int kt) {
        if (kt < NT) {
            const int kOff = kt * BK;
            const uint32_t st = sbase + (uint32_t)((kt % STAGES) * STAGE_B);
            const __half* ga = A1 + (size_t)(mBase + arow) * lda + kOff + acol * 8;
            #pragma unroll
            for (int c = 0; c < 4; ++c)
                cp16(st + (uint32_t)(arow * ROW_B + (acol + c) * 16), ga + c * 8);
            #pragma unroll
            for (int i = 0; i < 3; ++i) {
                const int chunk = tid + i * 256;           // < 768
                const int row = chunk >> 3, col = chunk & 7;
                cp16(st + (uint32_t)(PLANE_A + row * ROW_B + col * 16),
                     B1 + (size_t)(nBase + row) * ldb + kOff + col * 8);
            }
        }
        asm volatile("cp.async.commit_group;\n" ::: "memory");
    };

    for (int s = 0; s < STAGES - 1; ++s) load_tile(s);

    for (int kt = 0; kt < NT; ++kt) {
        asm volatile("cp.async.wait_group %0;\n" :: "n"(STAGES - 2) : "memory");
        __syncthreads();
        load_tile(kt + STAGES - 1);

        const uint32_t stA = sbase + (uint32_t)((kt % STAGES) * STAGE_B);
        const uint32_t stB = stA + (uint32_t)PLANE_A;

        #pragma unroll
        for (int k16 = 0; k16 < BK; k16 += 16) {
            uint32_t a[4][4], b[3][2];
            #pragma unroll
            for (int mi = 0; mi < 4; ++mi) {
                const uint32_t addr = stA +
                    ((uint32_t)(wm + mi * 16) + aRow) * ROW_B +
                    ((uint32_t)k16 + aKof) * 2;
                ldsm4(a[mi][0], a[mi][1], a[mi][2], a[mi][3], addr);
            }
            {   // n-tiles 0,1 via x4
                const uint32_t addr = stB +
                    ((uint32_t)wn + bRow) * ROW_B + ((uint32_t)k16 + bKof) * 2;
                ldsm4(b[0][0], b[0][1], b[1][0], b[1][1], addr);
            }
            {   // n-tile 2 via x2
                const uint32_t addr = stB +
                    ((uint32_t)(wn + 16) + b2Row) * ROW_B +
                    ((uint32_t)k16 + b2Kof) * 2;
                ldsm2(b[2][0], b[2][1], addr);
            }
            #pragma unroll
            for (int mi = 0; mi < 4; ++mi)
                #pragma unroll
                for (int ni = 0; ni < 3; ++ni)
                    mma16816(acc[mi][ni],
                             a[mi][0], a[mi][1], a[mi][2], a[mi][3],
                             b[ni][0], b[ni][1]);
        }
    }

    // -------- epilogue -------------------------------------------------------
    #pragma unroll
    for (int mi = 0; mi < 4; ++mi) {
        const int m0 = mBase + wm + mi * 16 + g;
        #pragma unroll
        for (int ni = 0; ni < 3; ++ni) {
            const int n0 = nBase + wn + ni * 8 + 2 * t;
            float v0x = acc[mi][ni][0], v0y = acc[mi][ni][1];
            float v1x = acc[mi][ni][2], v1y = acc[mi][ni][3];
            if (bias) {
                const float2 bv = *reinterpret_cast<const float2*>(bias + n0);
                v0x += bv.x; v0y += bv.y; v1x += bv.x; v1y += bv.y;
            }
            if (ADDM) {
                const float2 w0 =
                    *reinterpret_cast<const float2*>(Madd + (size_t)m0 * ldc + n0);
                const float2 w1 =
                    *reinterpret_cast<const float2*>(Madd + (size_t)(m0 + 8) * ldc + n0);
                v0x += w0.x; v0y += w0.y; v1x += w1.x; v1y += w1.y;
            }
            if (OUTH) {
                __half* C = (__half*)Cout;
                *reinterpret_cast<__half2*>(C + (size_t)m0 * ldc + n0) =
                    __floats2half2_rn(v0x, v0y);
                *reinterpret_cast<__half2*>(C + (size_t)(m0 + 8) * ldc + n0) =
                    __floats2half2_rn(v1x, v1y);
            } else {
                float* C = (float*)Cout;
                stcs2(C + (size_t)m0 * ldc + n0,       v0x, v0y);
                stcs2(C + (size_t)(m0 + 8) * ldc + n0, v1x, v1y);
            }
        }
    }
}

// ---------------- launch -----------------------------------------------------
extern "C" void kernel_launch(void* const* d_in, const int* in_sizes, int n_in,
                              void* d_out, int out_size) {
    const float* x  = (const float*)d_in[0];   // [4,4096,3072]
    const float* W  = (const float*)d_in[1];   // [3072,3072]
    const float* b  = (const float*)d_in[2];   // [3072]
    const float* lA = (const float*)d_in[3];   // [4,32,3072]
    const float* lB = (const float*)d_in[4];   // [4,3072,32]
    float* out = (float*)d_out;                // [4,4096,3072]

    void *xh, *Wph, *AfT, *Bph;
    cudaGetSymbolAddress(&xh,  g_xh);
    cudaGetSymbolAddress(&Wph, g_Wph);
    cudaGetSymbolAddress(&AfT, g_AfT);
    cudaGetSymbolAddress(&Bph, g_Bph);

    cudaFuncSetAttribute((const void*)gemm_f16<false, false>,
                         cudaFuncAttributeMaxDynamicSharedMemorySize, SMEM_B);
    cudaFuncSetAttribute((const void*)gemm_f16<true, true>,
                         cudaFuncAttributeMaxDynamicSharedMemorySize, SMEM_B);

    // 1) fp16 conversions + packs (x, A^T, Bp); W stays fp32 for the fold
    prep_kernel<<<4096, 256>>>(x, lA, lB);

    // 2) W' = W + Bp @ Aflat   (M=3072, N=3072, K=128) -> fp16 W'
    gemm_f16<true, true><<<dim3(D_DIM / BN, D_DIM / BM), NTHREADS, SMEM_B>>>(
        (const __half*)Bph, R_DIM, (const __half*)AfT, R_DIM, R_DIM,
        nullptr, W, Wph, D_DIM);

    // 3) out = x @ W'^T + b   (M=16384, N=3072, K=3072)
    gemm_f16<false, false><<<dim3(D_DIM / BN, M_ROWS / BM), NTHREADS, SMEM_B>>>(
        (const __half*)xh, D_DIM, (const __half*)Wph, D_DIM, D_DIM,
        b, nullptr, out, D_DIM);
}